// round 12
// baseline (speedup 1.0000x reference)
#include <cuda_runtime.h>
#include <cstdint>

#define B   8
#define D   512
#define L   4096
#define NH  8
#define HD  64
#define LP1 4097
#define ATT_SCALE 0.125f   // 1/sqrt(64)

// Scratch (device globals: no runtime allocation allowed)
__device__ float g_q[B * LP1 * D];
__device__ float g_k[B * LP1 * D];
__device__ float g_v[B * LP1 * D];
__device__ float g_att[B * L * D];   // (b, l, d) row-major
__device__ float g_attr[B * D];

// ---------------------------------------------------------------------------
// TF32 helpers
// ---------------------------------------------------------------------------
__device__ __forceinline__ unsigned f2t(float f) {
    unsigned r;
    asm("cvt.rna.tf32.f32 %0, %1;" : "=r"(r) : "f"(f));
    return r;
}

__device__ __forceinline__ void mma_tf32(float c[4], const unsigned a[4],
                                         const unsigned b[2]) {
    asm volatile(
        "mma.sync.aligned.m16n8k8.row.col.f32.tf32.tf32.f32 "
        "{%0,%1,%2,%3}, {%4,%5,%6,%7}, {%8,%9}, {%0,%1,%2,%3};"
        : "+f"(c[0]), "+f"(c[1]), "+f"(c[2]), "+f"(c[3])
        : "r"(a[0]), "r"(a[1]), "r"(a[2]), "r"(a[3]), "r"(b[0]), "r"(b[1]));
}

#define SPAD 136   // smem row pad: frag-load banks (8*tg + g) % 32 all distinct

// ---------------------------------------------------------------------------
// QKV projection (TF32 tensor cores).
//   out[b][l][j] = sum_d x[b][d][l] * W[d][j]
// 128x128 tile, BK=16, 128 threads (4 warps: 2m x 2n, 64x64 per warp),
// m16n8k8 TF32 mma, double-buffered smem.
// grid: (B*L/128, D/128, 3)
// ---------------------------------------------------------------------------
__global__ void __launch_bounds__(128, 2)
qkv_gemm(const float* __restrict__ x,
         const float* __restrict__ Wq,
         const float* __restrict__ Wk,
         const float* __restrict__ Wv) {
    __shared__ unsigned As[2][16][SPAD];   // [k][m=l]
    __shared__ unsigned Ws[2][16][SPAD];   // [k][n=j]

    int z = blockIdx.z;
    const float* W = (z == 0) ? Wq : (z == 1) ? Wk : Wv;
    float* out = (z == 0) ? g_q : (z == 1) ? g_k : g_v;

    int m0 = blockIdx.x * 128;
    int b  = m0 >> 12;
    int l0 = m0 & (L - 1);
    int j0 = blockIdx.y * 128;

    const float* xb = x + (size_t)b * D * L;
    int tid  = threadIdx.x;
    int lane = tid & 31, wid = tid >> 5;
    int g    = lane >> 2, tg = lane & 3;
    int wm   = wid & 1,  wn = wid >> 1;

    // Loader mapping: 4 float4 per thread per matrix per stage.
    int lr = tid >> 5;            // base row 0..3, rows lr + 4*i
    int c4 = (tid & 31) * 4;

    float acc[4][8][4] = {};

    // Prologue: stage 0
    #pragma unroll
    for (int i = 0; i < 4; i++) {
        int r = lr + i * 4;
        float4 a = *(const float4*)&xb[(size_t)r * L + l0 + c4];
        float4 w = *(const float4*)&W [(size_t)r * D + j0 + c4];
        *(uint4*)&As[0][r][c4] = make_uint4(f2t(a.x), f2t(a.y), f2t(a.z), f2t(a.w));
        *(uint4*)&Ws[0][r][c4] = make_uint4(f2t(w.x), f2t(w.y), f2t(w.z), f2t(w.w));
    }
    __syncthreads();

    int s = 0;
    for (int kt = 0; kt < D; kt += 16) {
        int ns = s ^ 1;
        if (kt + 16 < D) {
            int kn = kt + 16;
            #pragma unroll
            for (int i = 0; i < 4; i++) {
                int r = lr + i * 4;
                float4 a = *(const float4*)&xb[(size_t)(kn + r) * L + l0 + c4];
                float4 w = *(const float4*)&W [(size_t)(kn + r) * D + j0 + c4];
                *(uint4*)&As[ns][r][c4] = make_uint4(f2t(a.x), f2t(a.y), f2t(a.z), f2t(a.w));
                *(uint4*)&Ws[ns][r][c4] = make_uint4(f2t(w.x), f2t(w.y), f2t(w.z), f2t(w.w));
            }
        }
        #pragma unroll
        for (int ks = 0; ks < 2; ks++) {
            int k0 = ks * 8;
            unsigned afr[4][4], bfr[8][2];
            #pragma unroll
            for (int mt = 0; mt < 4; mt++) {
                int m = wm * 64 + mt * 16 + g;
                afr[mt][0] = As[s][k0 + tg    ][m];
                afr[mt][1] = As[s][k0 + tg    ][m + 8];
                afr[mt][2] = As[s][k0 + tg + 4][m];
                afr[mt][3] = As[s][k0 + tg + 4][m + 8];
            }
            #pragma unroll
            for (int nt = 0; nt < 8; nt++) {
                int n = wn * 64 + nt * 8 + g;
                bfr[nt][0] = Ws[s][k0 + tg    ][n];
                bfr[nt][1] = Ws[s][k0 + tg + 4][n];
            }
            #pragma unroll
            for (int mt = 0; mt < 4; mt++)
                #pragma unroll
                for (int nt = 0; nt < 8; nt++)
                    mma_tf32(acc[mt][nt], afr[mt], bfr[nt]);
        }
        __syncthreads();
        s = ns;
    }

    float* ob = out + (size_t)b * LP1 * D;
    #pragma unroll
    for (int mt = 0; mt < 4; mt++) {
        int row0 = l0 + wm * 64 + mt * 16 + g;
        #pragma unroll
        for (int nt = 0; nt < 8; nt++) {
            int col = j0 + wn * 64 + nt * 8 + tg * 2;
            *(float2*)&ob[(size_t)row0 * D + col] =
                make_float2(acc[mt][nt][0], acc[mt][nt][1]);
            *(float2*)&ob[(size_t)(row0 + 8) * D + col] =
                make_float2(acc[mt][nt][2], acc[mt][nt][3]);
        }
    }
}

// ---------------------------------------------------------------------------
// QKV projection for the relay token (fp32, tiny).
// grid: (3, B), block: 512
// ---------------------------------------------------------------------------
__global__ void qkv_relay(const float* __restrict__ y,
                          const float* __restrict__ Wq,
                          const float* __restrict__ Wk,
                          const float* __restrict__ Wv) {
    int z = blockIdx.x, b = blockIdx.y;
    const float* W = (z == 0) ? Wq : (z == 1) ? Wk : Wv;
    float* out = (z == 0) ? g_q : (z == 1) ? g_k : g_v;

    __shared__ float sy[D];
    int t = threadIdx.x;
    sy[t] = y[b * D + t];
    __syncthreads();

    float s = 0.f;
    for (int d = 0; d < D; d++) s += sy[d] * W[(size_t)d * D + t];
    out[(size_t)b * LP1 * D + (size_t)L * D + t] = s;
}

// ---------------------------------------------------------------------------
// Local windowed attention: per (b, l) block, warp w = head.
// grid: B*L blocks, 256 threads (8 warps).
// ---------------------------------------------------------------------------
__global__ void local_attn() {
    int m = blockIdx.x;
    int b = m >> 12, l = m & (L - 1);
    int head = threadIdx.x >> 5;
    int lane = threadIdx.x & 31;

    const float* qb = g_q + (size_t)b * LP1 * D;
    const float* kb = g_k + (size_t)b * LP1 * D;
    const float* vb = g_v + (size_t)b * LP1 * D;

    int hoff = head * HD + lane * 2;
    float2 qv = *(const float2*)(qb + (size_t)l * D + hoff);

    float s[4];
    int   lk[4];
    bool  valid[4];
    #pragma unroll
    for (int w = 0; w < 3; w++) {
        lk[w] = l - 1 + w;
        valid[w] = ((unsigned)lk[w] < (unsigned)L);
    }
    lk[3] = L; valid[3] = true;

    #pragma unroll
    for (int w = 0; w < 4; w++) {
        float sv = 0.f;
        if (valid[w]) {
            float2 kv = *(const float2*)(kb + (size_t)lk[w] * D + hoff);
            sv = qv.x * kv.x + qv.y * kv.y;
            #pragma unroll
            for (int o = 16; o > 0; o >>= 1)
                sv += __shfl_xor_sync(0xffffffffu, sv, o);
            sv *= ATT_SCALE;
        }
        s[w] = sv;        // padded key contributes score 0 (matches ref zero-pad)
    }

    float mx = fmaxf(fmaxf(s[0], s[1]), fmaxf(s[2], s[3]));
    float e[4], denom = 0.f;
    #pragma unroll
    for (int w = 0; w < 4; w++) { e[w] = expf(s[w] - mx); denom += e[w]; }
    float inv = 1.f / denom;

    float2 acc = make_float2(0.f, 0.f);
    #pragma unroll
    for (int w = 0; w < 4; w++) {
        if (valid[w]) {
            float2 vv = *(const float2*)(vb + (size_t)lk[w] * D + hoff);
            float a = e[w] * inv;
            acc.x += a * vv.x;
            acc.y += a * vv.y;
        }
    }
    *(float2*)(g_att + ((size_t)b * L + l) * D + hoff) = acc;
}

// ---------------------------------------------------------------------------
// Ring output projection (TF32): out[b][e][l] = sum_d WO[d][e]*att[b][l][d]+bO[e]
// C rows = e (m), cols = l (n). A = WO (k-major over d, contiguous e),
// B = att transposed into smem [d][l].
// 128x128 tile, 128 threads (4 warps 2x2, 64x64 per warp), double-buffered.
// grid: (L/128, D/128, B), 128 threads.
// ---------------------------------------------------------------------------
__global__ void __launch_bounds__(128, 2)
ring_gemm(const float* __restrict__ WO,
          const float* __restrict__ bO,
          float* __restrict__ out) {
    __shared__ unsigned As[2][16][SPAD];   // [k=d][m=e]  from WO
    __shared__ unsigned Bs[2][16][SPAD];   // [k=d][n=l]  transposed from att

    int b  = blockIdx.z;
    int l0 = blockIdx.x * 128;
    int e0 = blockIdx.y * 128;
    const float* ab = g_att + (size_t)b * L * D;

    int tid  = threadIdx.x;
    int lane = tid & 31, wid = tid >> 5;
    int g    = lane >> 2, tg = lane & 3;
    int wm   = wid & 1,  wn = wid >> 1;

    // A loader: 4 float4 per thread per stage (rows lr + 4i, cols c4..c4+3)
    int lr = tid >> 5;
    int c4 = (tid & 31) * 4;
    // B transpose loader: thread li = tid covers l-row li, 4 d-quads
    int li = tid;

    float acc[4][8][4] = {};

    // Prologue
    {
        #pragma unroll
        for (int i = 0; i < 4; i++) {
            int r = lr + i * 4;
            float4 w = *(const float4*)&WO[(size_t)r * D + e0 + c4];
            *(uint4*)&As[0][r][c4] = make_uint4(f2t(w.x), f2t(w.y), f2t(w.z), f2t(w.w));
        }
        #pragma unroll
        for (int q = 0; q < 4; q++) {
            float4 v = *(const float4*)&ab[(size_t)(l0 + li) * D + q * 4];
            Bs[0][q * 4 + 0][li] = f2t(v.x); Bs[0][q * 4 + 1][li] = f2t(v.y);
            Bs[0][q * 4 + 2][li] = f2t(v.z); Bs[0][q * 4 + 3][li] = f2t(v.w);
        }
    }
    __syncthreads();

    int s = 0;
    for (int kt = 0; kt < D; kt += 16) {
        int ns = s ^ 1;
        if (kt + 16 < D) {
            int kn = kt + 16;
            #pragma unroll
            for (int i = 0; i < 4; i++) {
                int r = lr + i * 4;
                float4 w = *(const float4*)&WO[(size_t)(kn + r) * D + e0 + c4];
                *(uint4*)&As[ns][r][c4] = make_uint4(f2t(w.x), f2t(w.y), f2t(w.z), f2t(w.w));
            }
            #pragma unroll
            for (int q = 0; q < 4; q++) {
                float4 v = *(const float4*)&ab[(size_t)(l0 + li) * D + kn + q * 4];
                Bs[ns][q * 4 + 0][li] = f2t(v.x); Bs[ns][q * 4 + 1][li] = f2t(v.y);
                Bs[ns][q * 4 + 2][li] = f2t(v.z); Bs[ns][q * 4 + 3][li] = f2t(v.w);
            }
        }
        #pragma unroll
        for (int ks = 0; ks < 2; ks++) {
            int k0 = ks * 8;
            unsigned afr[4][4], bfr[8][2];
            #pragma unroll
            for (int mt = 0; mt < 4; mt++) {
                int m = wm * 64 + mt * 16 + g;
                afr[mt][0] = As[s][k0 + tg    ][m];
                afr[mt][1] = As[s][k0 + tg    ][m + 8];
                afr[mt][2] = As[s][k0 + tg + 4][m];
                afr[mt][3] = As[s][k0 + tg + 4][m + 8];
            }
            #pragma unroll
            for (int nt = 0; nt < 8; nt++) {
                int n = wn * 64 + nt * 8 + g;
                bfr[nt][0] = Bs[s][k0 + tg    ][n];
                bfr[nt][1] = Bs[s][k0 + tg + 4][n];
            }
            #pragma unroll
            for (int mt = 0; mt < 4; mt++)
                #pragma unroll
                for (int nt = 0; nt < 8; nt++)
                    mma_tf32(acc[mt][nt], afr[mt], bfr[nt]);
        }
        __syncthreads();
        s = ns;
    }

    float* outb = out + (size_t)b * D * L;
    #pragma unroll
    for (int mt = 0; mt < 4; mt++) {
        int e = e0 + wm * 64 + mt * 16 + g;
        float bias0 = bO[e];
        float bias1 = bO[e + 8];
        #pragma unroll
        for (int nt = 0; nt < 8; nt++) {
            int col = l0 + wn * 64 + nt * 8 + tg * 2;
            *(float2*)&outb[(size_t)e * L + col] =
                make_float2(acc[mt][nt][0] + bias0, acc[mt][nt][1] + bias0);
            *(float2*)&outb[(size_t)(e + 8) * L + col] =
                make_float2(acc[mt][nt][2] + bias1, acc[mt][nt][3] + bias1);
        }
    }
}

// ---------------------------------------------------------------------------
// Relay attention: relay query attends over all L+1 keys of its head.
// grid: (NH, B), 256 threads.
// ---------------------------------------------------------------------------
__global__ void relay_attn() {
    int n = blockIdx.x, b = blockIdx.y;
    __shared__ float sq[HD];
    __shared__ float sc[LP1];
    __shared__ float red[256];
    __shared__ float pacc[4][64];

    int tid = threadIdx.x;
    const float* qb = g_q + (size_t)b * LP1 * D;
    const float* kb = g_k + (size_t)b * LP1 * D;
    const float* vb = g_v + (size_t)b * LP1 * D;
    int hoff = n * HD;

    if (tid < HD) sq[tid] = qb[(size_t)L * D + hoff + tid];
    __syncthreads();

    float lmax = -1e30f;
    for (int l = tid; l < LP1; l += 256) {
        const float* kr = kb + (size_t)l * D + hoff;
        float dot = 0.f;
        #pragma unroll 8
        for (int d = 0; d < HD; d++) dot += sq[d] * kr[d];
        dot *= ATT_SCALE;
        sc[l] = dot;
        lmax = fmaxf(lmax, dot);
    }
    red[tid] = lmax; __syncthreads();
    for (int s = 128; s > 0; s >>= 1) {
        if (tid < s) red[tid] = fmaxf(red[tid], red[tid + s]);
        __syncthreads();
    }
    float mx = red[0];
    __syncthreads();

    float lsum = 0.f;
    for (int l = tid; l < LP1; l += 256) {
        float e = expf(sc[l] - mx);
        sc[l] = e;
        lsum += e;
    }
    red[tid] = lsum; __syncthreads();
    for (int s = 128; s > 0; s >>= 1) {
        if (tid < s) red[tid] += red[tid + s];
        __syncthreads();
    }
    float inv = 1.f / red[0];
    __syncthreads();

    int d = tid & 63, g = tid >> 6;
    float part = 0.f;
    for (int l = g; l < LP1; l += 4)
        part += sc[l] * vb[(size_t)l * D + hoff + d];
    pacc[g][d] = part;
    __syncthreads();
    if (tid < 64) {
        float tot = (pacc[0][tid] + pacc[1][tid] + pacc[2][tid] + pacc[3][tid]) * inv;
        g_attr[b * D + hoff + tid] = tot;
    }
}

// ---------------------------------------------------------------------------
// Relay output projection.
// grid: B, block: 512.
// ---------------------------------------------------------------------------
__global__ void relay_out(const float* __restrict__ WOs,
                          const float* __restrict__ bOs,
                          float* __restrict__ out) {
    int b = blockIdx.x;
    __shared__ float sa[D];
    int t = threadIdx.x;
    sa[t] = g_attr[b * D + t];
    __syncthreads();
    float s = bOs[t];
    for (int d = 0; d < D; d++) s += sa[d] * WOs[(size_t)d * D + t];
    out[(size_t)B * D * L + b * D + t] = s;
}

// ---------------------------------------------------------------------------
extern "C" void kernel_launch(void* const* d_in, const int* in_sizes, int n_in,
                              void* d_out, int out_size) {
    const float* x       = (const float*)d_in[0];
    const float* y       = (const float*)d_in[1];
    const float* Wq      = (const float*)d_in[2];
    const float* Wk      = (const float*)d_in[3];
    const float* Wv      = (const float*)d_in[4];
    const float* WO_ring = (const float*)d_in[5];
    const float* bO_ring = (const float*)d_in[6];
    const float* WO_star = (const float*)d_in[7];
    const float* bO_star = (const float*)d_in[8];
    float* out = (float*)d_out;

    qkv_gemm <<<dim3(B * L / 128, D / 128, 3), 128>>>(x, Wq, Wk, Wv);
    qkv_relay<<<dim3(3, B), D>>>(y, Wq, Wk, Wv);
    local_attn<<<B * L, 256>>>();
    ring_gemm<<<dim3(L / 128, D / 128, B), 128>>>(WO_ring, bO_ring, out);
    relay_attn<<<dim3(NH, B), 256>>>();
    relay_out<<<B, D>>>(WO_star, bO_star, out);
}

// round 13
// speedup vs baseline: 1.2800x; 1.2800x over previous
#include <cuda_runtime.h>
#include <cstdint>

#define B   8
#define D   512
#define L   4096
#define NH  8
#define HD  64
#define LP1 4097
#define RSPLIT 16
#define RCHUNK 257          // ceil(4097/16)
#define ATT_SCALE 0.125f    // 1/sqrt(64)

// Scratch (device globals: no runtime allocation allowed)
__device__ float g_q[B * LP1 * D];
__device__ float g_k[B * LP1 * D];
__device__ float g_v[B * LP1 * D];
__device__ float g_att[B * L * D];   // (b, l, d) row-major
__device__ float g_attr[B * D];
__device__ float g_rm[B * NH * RSPLIT];
__device__ float g_rs[B * NH * RSPLIT];
__device__ float g_ro[B * NH * RSPLIT * HD];

// ---------------------------------------------------------------------------
// TF32 helpers
// ---------------------------------------------------------------------------
__device__ __forceinline__ unsigned f2t(float f) {
    unsigned r;
    asm("cvt.rna.tf32.f32 %0, %1;" : "=r"(r) : "f"(f));
    return r;
}

__device__ __forceinline__ void mma_tf32(float c[4], const unsigned a[4],
                                         const unsigned b[2]) {
    asm volatile(
        "mma.sync.aligned.m16n8k8.row.col.f32.tf32.tf32.f32 "
        "{%0,%1,%2,%3}, {%4,%5,%6,%7}, {%8,%9}, {%0,%1,%2,%3};"
        : "+f"(c[0]), "+f"(c[1]), "+f"(c[2]), "+f"(c[3])
        : "r"(a[0]), "r"(a[1]), "r"(a[2]), "r"(a[3]), "r"(b[0]), "r"(b[1]));
}

#define SPAD 136   // smem row pad: frag-load banks (8*tg + g) % 32 all distinct

// ---------------------------------------------------------------------------
// QKV projection (TF32 tensor cores) — identical to the 951us R6 config.
// 128x128 tile, BK=16, 256 threads (8 warps: 2m x 4n, 64x32 per warp).
// grid: (B*L/128, D/128, 3)
// ---------------------------------------------------------------------------
__global__ void __launch_bounds__(256, 2)
qkv_gemm(const float* __restrict__ x,
         const float* __restrict__ Wq,
         const float* __restrict__ Wk,
         const float* __restrict__ Wv) {
    __shared__ unsigned As[2][16][SPAD];   // [k][m=l]
    __shared__ unsigned Ws[2][16][SPAD];   // [k][n=j]

    int z = blockIdx.z;
    const float* W = (z == 0) ? Wq : (z == 1) ? Wk : Wv;
    float* out = (z == 0) ? g_q : (z == 1) ? g_k : g_v;

    int m0 = blockIdx.x * 128;
    int b  = m0 >> 12;
    int l0 = m0 & (L - 1);
    int j0 = blockIdx.y * 128;

    const float* xb = x + (size_t)b * D * L;
    int tid  = threadIdx.x;
    int lane = tid & 31, wid = tid >> 5;
    int g    = lane >> 2, tg = lane & 3;
    int wm   = wid & 1,  wn = wid >> 1;

    int r0 = wid, r1 = wid + 8, c4 = lane * 4;

    float acc[4][4][4] = {};

    {
        float4 a0 = *(const float4*)&xb[(size_t)r0 * L + l0 + c4];
        float4 a1 = *(const float4*)&xb[(size_t)r1 * L + l0 + c4];
        float4 w0 = *(const float4*)&W [(size_t)r0 * D + j0 + c4];
        float4 w1 = *(const float4*)&W [(size_t)r1 * D + j0 + c4];
        *(uint4*)&As[0][r0][c4] = make_uint4(f2t(a0.x), f2t(a0.y), f2t(a0.z), f2t(a0.w));
        *(uint4*)&As[0][r1][c4] = make_uint4(f2t(a1.x), f2t(a1.y), f2t(a1.z), f2t(a1.w));
        *(uint4*)&Ws[0][r0][c4] = make_uint4(f2t(w0.x), f2t(w0.y), f2t(w0.z), f2t(w0.w));
        *(uint4*)&Ws[0][r1][c4] = make_uint4(f2t(w1.x), f2t(w1.y), f2t(w1.z), f2t(w1.w));
    }
    __syncthreads();

    int s = 0;
    for (int kt = 0; kt < D; kt += 16) {
        int ns = s ^ 1;
        if (kt + 16 < D) {
            int kn = kt + 16;
            float4 a0 = *(const float4*)&xb[(size_t)(kn + r0) * L + l0 + c4];
            float4 a1 = *(const float4*)&xb[(size_t)(kn + r1) * L + l0 + c4];
            float4 w0 = *(const float4*)&W [(size_t)(kn + r0) * D + j0 + c4];
            float4 w1 = *(const float4*)&W [(size_t)(kn + r1) * D + j0 + c4];
            *(uint4*)&As[ns][r0][c4] = make_uint4(f2t(a0.x), f2t(a0.y), f2t(a0.z), f2t(a0.w));
            *(uint4*)&As[ns][r1][c4] = make_uint4(f2t(a1.x), f2t(a1.y), f2t(a1.z), f2t(a1.w));
            *(uint4*)&Ws[ns][r0][c4] = make_uint4(f2t(w0.x), f2t(w0.y), f2t(w0.z), f2t(w0.w));
            *(uint4*)&Ws[ns][r1][c4] = make_uint4(f2t(w1.x), f2t(w1.y), f2t(w1.z), f2t(w1.w));
        }
        #pragma unroll
        for (int ks = 0; ks < 2; ks++) {
            int k0 = ks * 8;
            unsigned afr[4][4], bfr[4][2];
            #pragma unroll
            for (int mt = 0; mt < 4; mt++) {
                int m = wm * 64 + mt * 16 + g;
                afr[mt][0] = As[s][k0 + tg    ][m];
                afr[mt][1] = As[s][k0 + tg    ][m + 8];
                afr[mt][2] = As[s][k0 + tg + 4][m];
                afr[mt][3] = As[s][k0 + tg + 4][m + 8];
            }
            #pragma unroll
            for (int nt = 0; nt < 4; nt++) {
                int n = wn * 32 + nt * 8 + g;
                bfr[nt][0] = Ws[s][k0 + tg    ][n];
                bfr[nt][1] = Ws[s][k0 + tg + 4][n];
            }
            #pragma unroll
            for (int mt = 0; mt < 4; mt++)
                #pragma unroll
                for (int nt = 0; nt < 4; nt++)
                    mma_tf32(acc[mt][nt], afr[mt], bfr[nt]);
        }
        __syncthreads();
        s = ns;
    }

    float* ob = out + (size_t)b * LP1 * D;
    #pragma unroll
    for (int mt = 0; mt < 4; mt++) {
        int row0 = l0 + wm * 64 + mt * 16 + g;
        #pragma unroll
        for (int nt = 0; nt < 4; nt++) {
            int col = j0 + wn * 32 + nt * 8 + tg * 2;
            *(float2*)&ob[(size_t)row0 * D + col] =
                make_float2(acc[mt][nt][0], acc[mt][nt][1]);
            *(float2*)&ob[(size_t)(row0 + 8) * D + col] =
                make_float2(acc[mt][nt][2], acc[mt][nt][3]);
        }
    }
}

// ---------------------------------------------------------------------------
// QKV projection for the relay token. grid: (3, B), block: 512
// ---------------------------------------------------------------------------
__global__ void qkv_relay(const float* __restrict__ y,
                          const float* __restrict__ Wq,
                          const float* __restrict__ Wk,
                          const float* __restrict__ Wv) {
    int z = blockIdx.x, b = blockIdx.y;
    const float* W = (z == 0) ? Wq : (z == 1) ? Wk : Wv;
    float* out = (z == 0) ? g_q : (z == 1) ? g_k : g_v;

    __shared__ float sy[D];
    int t = threadIdx.x;
    sy[t] = y[b * D + t];
    __syncthreads();

    float s = 0.f;
    for (int d = 0; d < D; d++) s += sy[d] * W[(size_t)d * D + t];
    out[(size_t)b * LP1 * D + (size_t)L * D + t] = s;
}

// ---------------------------------------------------------------------------
// Local windowed attention, smem-tiled.
// grid: (L/64, NH, B), 256 threads (8 warps; warp handles 8 tokens).
// smem holds K/V rows for tokens [l0-1, l0+64] (rows 0..65) + relay (row 66),
// head-slice only (64 floats/row). Out-of-range rows are zero => score 0 and
// zero V contribution, exactly matching the reference zero-pad.
// ---------------------------------------------------------------------------
__global__ void __launch_bounds__(256, 4)
local_attn() {
    __shared__ float2 sk[67][32];
    __shared__ float2 sv[67][32];

    int l0   = blockIdx.x * 64;
    int head = blockIdx.y;
    int b    = blockIdx.z;
    int hoff = head * HD;
    int tid  = threadIdx.x;

    const float* kb = g_k + (size_t)b * LP1 * D + hoff;
    const float* vb = g_v + (size_t)b * LP1 * D + hoff;

    // Load 67 rows x 64 floats (16 float4 per row) for k and v.
    for (int idx = tid; idx < 67 * 16; idx += 256) {
        int r  = idx >> 4;
        int c  = idx & 15;
        float4 kv = make_float4(0.f, 0.f, 0.f, 0.f), vv = kv;
        int tok = (r == 66) ? L : (l0 - 1 + r);
        if (r == 66 || (unsigned)(l0 - 1 + r) < (unsigned)L) {
            kv = *(const float4*)&kb[(size_t)tok * D + c * 4];
            vv = *(const float4*)&vb[(size_t)tok * D + c * 4];
        }
        ((float4*)sk[r])[c] = kv;
        ((float4*)sv[r])[c] = vv;
    }
    __syncthreads();

    int w = tid >> 5, lane = tid & 31;
    const float* qb = g_q + (size_t)b * LP1 * D + hoff;

    #pragma unroll
    for (int t = 0; t < 8; t++) {
        int j = w * 8 + t;          // local token
        int l = l0 + j;
        float2 qv = *(const float2*)&qb[(size_t)l * D + lane * 2];

        float s[4];
        #pragma unroll
        for (int w4 = 0; w4 < 4; w4++) {
            int row = (w4 < 3) ? (j + w4) : 66;
            float2 kv = sk[row][lane];
            float sv_ = qv.x * kv.x + qv.y * kv.y;
            #pragma unroll
            for (int o = 16; o > 0; o >>= 1)
                sv_ += __shfl_xor_sync(0xffffffffu, sv_, o);
            s[w4] = sv_ * ATT_SCALE;
        }

        float mx = fmaxf(fmaxf(s[0], s[1]), fmaxf(s[2], s[3]));
        float e[4], denom = 0.f;
        #pragma unroll
        for (int w4 = 0; w4 < 4; w4++) { e[w4] = expf(s[w4] - mx); denom += e[w4]; }
        float inv = 1.f / denom;

        float2 acc = make_float2(0.f, 0.f);
        #pragma unroll
        for (int w4 = 0; w4 < 4; w4++) {
            int row = (w4 < 3) ? (j + w4) : 66;
            float2 vv = sv[row][lane];
            float a = e[w4] * inv;
            acc.x += a * vv.x;
            acc.y += a * vv.y;
        }
        *(float2*)&g_att[((size_t)b * L + l) * D + hoff + lane * 2] = acc;
    }
}

// ---------------------------------------------------------------------------
// Ring output projection (TF32) — identical to the 951us R6 config.
// grid: (L/128, D/128, B), 256 threads.
// ---------------------------------------------------------------------------
__global__ void __launch_bounds__(256, 2)
ring_gemm(const float* __restrict__ WO,
          const float* __restrict__ bO,
          float* __restrict__ out) {
    __shared__ unsigned As[2][16][SPAD];   // [k=d][m=e]  from WO
    __shared__ unsigned Bs[2][16][SPAD];   // [k=d][n=l]  transposed from att

    int b  = blockIdx.z;
    int l0 = blockIdx.x * 128;
    int e0 = blockIdx.y * 128;
    const float* ab = g_att + (size_t)b * L * D;

    int tid  = threadIdx.x;
    int lane = tid & 31, wid = tid >> 5;
    int g    = lane >> 2, tg = lane & 3;
    int wm   = wid & 1,  wn = wid >> 1;

    int r0 = wid, r1 = wid + 8, c4 = lane * 4;
    int li0 = tid >> 2, li1 = li0 + 64, dq = tid & 3;

    float acc[4][4][4] = {};

    {
        float4 w0 = *(const float4*)&WO[(size_t)r0 * D + e0 + c4];
        float4 w1 = *(const float4*)&WO[(size_t)r1 * D + e0 + c4];
        *(uint4*)&As[0][r0][c4] = make_uint4(f2t(w0.x), f2t(w0.y), f2t(w0.z), f2t(w0.w));
        *(uint4*)&As[0][r1][c4] = make_uint4(f2t(w1.x), f2t(w1.y), f2t(w1.z), f2t(w1.w));
        float4 v0 = *(const float4*)&ab[(size_t)(l0 + li0) * D + dq * 4];
        float4 v1 = *(const float4*)&ab[(size_t)(l0 + li1) * D + dq * 4];
        Bs[0][dq * 4 + 0][li0] = f2t(v0.x); Bs[0][dq * 4 + 1][li0] = f2t(v0.y);
        Bs[0][dq * 4 + 2][li0] = f2t(v0.z); Bs[0][dq * 4 + 3][li0] = f2t(v0.w);
        Bs[0][dq * 4 + 0][li1] = f2t(v1.x); Bs[0][dq * 4 + 1][li1] = f2t(v1.y);
        Bs[0][dq * 4 + 2][li1] = f2t(v1.z); Bs[0][dq * 4 + 3][li1] = f2t(v1.w);
    }
    __syncthreads();

    int s = 0;
    for (int kt = 0; kt < D; kt += 16) {
        int ns = s ^ 1;
        if (kt + 16 < D) {
            int kn = kt + 16;
            float4 w0 = *(const float4*)&WO[(size_t)(kn + r0) * D + e0 + c4];
            float4 w1 = *(const float4*)&WO[(size_t)(kn + r1) * D + e0 + c4];
            *(uint4*)&As[ns][r0][c4] = make_uint4(f2t(w0.x), f2t(w0.y), f2t(w0.z), f2t(w0.w));
            *(uint4*)&As[ns][r1][c4] = make_uint4(f2t(w1.x), f2t(w1.y), f2t(w1.z), f2t(w1.w));
            float4 v0 = *(const float4*)&ab[(size_t)(l0 + li0) * D + kn + dq * 4];
            float4 v1 = *(const float4*)&ab[(size_t)(l0 + li1) * D + kn + dq * 4];
            Bs[ns][dq * 4 + 0][li0] = f2t(v0.x); Bs[ns][dq * 4 + 1][li0] = f2t(v0.y);
            Bs[ns][dq * 4 + 2][li0] = f2t(v0.z); Bs[ns][dq * 4 + 3][li0] = f2t(v0.w);
            Bs[ns][dq * 4 + 0][li1] = f2t(v1.x); Bs[ns][dq * 4 + 1][li1] = f2t(v1.y);
            Bs[ns][dq * 4 + 2][li1] = f2t(v1.z); Bs[ns][dq * 4 + 3][li1] = f2t(v1.w);
        }
        #pragma unroll
        for (int ks = 0; ks < 2; ks++) {
            int k0 = ks * 8;
            unsigned afr[4][4], bfr[4][2];
            #pragma unroll
            for (int mt = 0; mt < 4; mt++) {
                int m = wm * 64 + mt * 16 + g;
                afr[mt][0] = As[s][k0 + tg    ][m];
                afr[mt][1] = As[s][k0 + tg    ][m + 8];
                afr[mt][2] = As[s][k0 + tg + 4][m];
                afr[mt][3] = As[s][k0 + tg + 4][m + 8];
            }
            #pragma unroll
            for (int nt = 0; nt < 4; nt++) {
                int n = wn * 32 + nt * 8 + g;
                bfr[nt][0] = Bs[s][k0 + tg    ][n];
                bfr[nt][1] = Bs[s][k0 + tg + 4][n];
            }
            #pragma unroll
            for (int mt = 0; mt < 4; mt++)
                #pragma unroll
                for (int nt = 0; nt < 4; nt++)
                    mma_tf32(acc[mt][nt], afr[mt], bfr[nt]);
        }
        __syncthreads();
        s = ns;
    }

    float* outb = out + (size_t)b * D * L;
    #pragma unroll
    for (int mt = 0; mt < 4; mt++) {
        int e = e0 + wm * 64 + mt * 16 + g;
        float bias0 = bO[e];
        float bias1 = bO[e + 8];
        #pragma unroll
        for (int nt = 0; nt < 4; nt++) {
            int col = l0 + wn * 32 + nt * 8 + tg * 2;
            *(float2*)&outb[(size_t)e * L + col] =
                make_float2(acc[mt][nt][0] + bias0, acc[mt][nt][1] + bias0);
            *(float2*)&outb[(size_t)(e + 8) * L + col] =
                make_float2(acc[mt][nt][2] + bias1, acc[mt][nt][3] + bias1);
        }
    }
}

// ---------------------------------------------------------------------------
// Relay attention, split-K partials.
// grid: (NH, B, RSPLIT), 256 threads. Each split covers <=257 tokens and
// emits (local max m, local sum s, local weighted V o[64]).
// ---------------------------------------------------------------------------
__global__ void relay_partial() {
    int n = blockIdx.x, b = blockIdx.y, z = blockIdx.z;
    int start = z * RCHUNK;
    int end   = min(start + RCHUNK, LP1);

    __shared__ float sq[HD];
    __shared__ float sc[RCHUNK];
    __shared__ float red[256];
    __shared__ float pacc[4][64];

    int tid = threadIdx.x;
    const float* qb = g_q + (size_t)b * LP1 * D;
    const float* kb = g_k + (size_t)b * LP1 * D;
    const float* vb = g_v + (size_t)b * LP1 * D;
    int hoff = n * HD;

    if (tid < HD) sq[tid] = qb[(size_t)L * D + hoff + tid];
    __syncthreads();

    float lmax = -1e30f;
    for (int l = start + tid; l < end; l += 256) {
        const float* kr = kb + (size_t)l * D + hoff;
        float dot = 0.f;
        #pragma unroll 8
        for (int d = 0; d < HD; d++) dot += sq[d] * kr[d];
        dot *= ATT_SCALE;
        sc[l - start] = dot;
        lmax = fmaxf(lmax, dot);
    }
    red[tid] = lmax; __syncthreads();
    for (int s = 128; s > 0; s >>= 1) {
        if (tid < s) red[tid] = fmaxf(red[tid], red[tid + s]);
        __syncthreads();
    }
    float mx = red[0];
    __syncthreads();

    float lsum = 0.f;
    for (int l = start + tid; l < end; l += 256) {
        float e = expf(sc[l - start] - mx);
        sc[l - start] = e;
        lsum += e;
    }
    red[tid] = lsum; __syncthreads();
    for (int s = 128; s > 0; s >>= 1) {
        if (tid < s) red[tid] += red[tid + s];
        __syncthreads();
    }
    float sum = red[0];
    __syncthreads();

    int d = tid & 63, g = tid >> 6;
    float part = 0.f;
    for (int l = start + g; l < end; l += 4)
        part += sc[l - start] * vb[(size_t)l * D + hoff + d];
    pacc[g][d] = part;
    __syncthreads();

    int idx = (b * NH + n) * RSPLIT + z;
    if (tid < 64)
        g_ro[(size_t)idx * HD + tid] =
            pacc[0][tid] + pacc[1][tid] + pacc[2][tid] + pacc[3][tid];
    if (tid == 0) { g_rm[idx] = mx; g_rs[idx] = sum; }
}

// ---------------------------------------------------------------------------
// Relay combine: merge RSPLIT partials (exact flash-attention merge).
// grid: B, 512 threads (thread = (head n, dim d)).
// ---------------------------------------------------------------------------
__global__ void relay_combine() {
    int b = blockIdx.x;
    int t = threadIdx.x;
    int n = t >> 6, d = t & 63;
    int base = (b * NH + n) * RSPLIT;

    float M = -1e30f;
    #pragma unroll
    for (int i = 0; i < RSPLIT; i++) M = fmaxf(M, g_rm[base + i]);
    float S = 0.f, O = 0.f;
    #pragma unroll
    for (int i = 0; i < RSPLIT; i++) {
        float w = expf(g_rm[base + i] - M);
        S += g_rs[base + i] * w;
        O += g_ro[(size_t)(base + i) * HD + d] * w;
    }
    g_attr[b * D + n * HD + d] = O / S;
}

// ---------------------------------------------------------------------------
// Relay output projection. grid: B, block: 512.
// ---------------------------------------------------------------------------
__global__ void relay_out(const float* __restrict__ WOs,
                          const float* __restrict__ bOs,
                          float* __restrict__ out) {
    int b = blockIdx.x;
    __shared__ float sa[D];
    int t = threadIdx.x;
    sa[t] = g_attr[b * D + t];
    __syncthreads();
    float s = bOs[t];
    for (int d = 0; d < D; d++) s += sa[d] * WOs[(size_t)d * D + t];
    out[(size_t)B * D * L + b * D + t] = s;
}

// ---------------------------------------------------------------------------
extern "C" void kernel_launch(void* const* d_in, const int* in_sizes, int n_in,
                              void* d_out, int out_size) {
    const float* x       = (const float*)d_in[0];
    const float* y       = (const float*)d_in[1];
    const float* Wq      = (const float*)d_in[2];
    const float* Wk      = (const float*)d_in[3];
    const float* Wv      = (const float*)d_in[4];
    const float* WO_ring = (const float*)d_in[5];
    const float* bO_ring = (const float*)d_in[6];
    const float* WO_star = (const float*)d_in[7];
    const float* bO_star = (const float*)d_in[8];
    float* out = (float*)d_out;

    qkv_gemm <<<dim3(B * L / 128, D / 128, 3), 256>>>(x, Wq, Wk, Wv);
    qkv_relay<<<dim3(3, B), D>>>(y, Wq, Wk, Wv);
    local_attn<<<dim3(L / 64, NH, B), 256>>>();
    relay_partial<<<dim3(NH, B, RSPLIT), 256>>>();
    ring_gemm<<<dim3(L / 128, D / 128, B), 256>>>(WO_ring, bO_ring, out);
    relay_combine<<<B, 512>>>();
    relay_out<<<B, D>>>(WO_star, bO_star, out);
}

// round 15
// speedup vs baseline: 1.6015x; 1.2512x over previous
#include <cuda_runtime.h>
#include <cstdint>

#define B   8
#define D   512
#define L   4096
#define NH  8
#define HD  64
#define LP1 4097
#define RSPLIT 16
#define RCHUNK 257
#define ATT_SCALE 0.125f

// Scratch (device globals: no runtime allocation allowed)
__device__ float g_q[B * LP1 * D];
__device__ float g_k[B * LP1 * D];
__device__ float g_v[B * LP1 * D];
__device__ float g_att[B * D * L];   // TRANSPOSED: (b, d, l)
__device__ float g_attr[B * D];
__device__ float g_rm[B * NH * RSPLIT];
__device__ float g_rs[B * NH * RSPLIT];
__device__ float g_ro[B * NH * RSPLIT * HD];

// ---------------------------------------------------------------------------
// TF32 + cp.async helpers
// ---------------------------------------------------------------------------
__device__ __forceinline__ unsigned f2t(float f) {
    unsigned r;
    asm("cvt.rna.tf32.f32 %0, %1;" : "=r"(r) : "f"(f));
    return r;
}
__device__ __forceinline__ void mma_tf32(float c[4], const unsigned a[4],
                                         const unsigned b[2]) {
    asm volatile(
        "mma.sync.aligned.m16n8k8.row.col.f32.tf32.tf32.f32 "
        "{%0,%1,%2,%3}, {%4,%5,%6,%7}, {%8,%9}, {%0,%1,%2,%3};"
        : "+f"(c[0]), "+f"(c[1]), "+f"(c[2]), "+f"(c[3])
        : "r"(a[0]), "r"(a[1]), "r"(a[2]), "r"(a[3]), "r"(b[0]), "r"(b[1]));
}
__device__ __forceinline__ uint32_t smem_u32(const void* p) {
    uint32_t a;
    asm("{ .reg .u64 t; cvta.to.shared.u64 t, %1; cvt.u32.u64 %0, t; }"
        : "=r"(a) : "l"(p));
    return a;
}
__device__ __forceinline__ void cpa16(float* dst, const float* src) {
    asm volatile("cp.async.cg.shared.global [%0], [%1], 16;"
                 :: "r"(smem_u32(dst)), "l"(src) : "memory");
}
#define CPA_COMMIT() asm volatile("cp.async.commit_group;" ::: "memory")
#define CPA_WAIT2()  asm volatile("cp.async.wait_group 2;"  ::: "memory")

#define SPAD 136                 // smem row pad (floats)
#define STG_F (16 * SPAD)        // floats per stage per matrix
#define GEMM_SHM (4 * STG_F * 2 * 4)   // 4 stages x 2 matrices, bytes = 69632

// ---------------------------------------------------------------------------
// QKV projection (TF32 mma.sync + 4-stage cp.async).
//   out[b][l][j] = sum_d x[b][d][l] * W[d][j]
// 128x128 tile, BK=16, 256 threads (8 warps 2m x 4n, 64x32 per warp).
// grid: (B*L/128, D/128, 3)
// ---------------------------------------------------------------------------
__global__ void __launch_bounds__(256, 2)
qkv_gemm(const float* __restrict__ x,
         const float* __restrict__ Wq,
         const float* __restrict__ Wk,
         const float* __restrict__ Wv) {
    extern __shared__ float sm[];
    float* As = sm;                 // [4][16][SPAD]  (k x m=l)
    float* Bs = sm + 4 * STG_F;     // [4][16][SPAD]  (k x n=j)

    int z = blockIdx.z;
    const float* W = (z == 0) ? Wq : (z == 1) ? Wk : Wv;
    float* out = (z == 0) ? g_q : (z == 1) ? g_k : g_v;

    int m0 = blockIdx.x * 128;
    int b  = m0 >> 12;
    int l0 = m0 & (L - 1);
    int j0 = blockIdx.y * 128;
    const float* xb = x + (size_t)b * D * L;

    int tid  = threadIdx.x;
    int lane = tid & 31, wid = tid >> 5;
    int g    = lane >> 2, tg = lane & 3;
    int wm   = wid & 1,  wn = wid >> 1;
    int r0 = wid, r1 = wid + 8, c4 = lane * 4;

    float acc[4][4][4] = {};

    // Prologue: issue 3 stages
    #pragma unroll
    for (int p = 0; p < 3; p++) {
        int kt = p * 16;
        float* Ad = As + p * STG_F;
        float* Bd = Bs + p * STG_F;
        cpa16(Ad + r0 * SPAD + c4, &xb[(size_t)(kt + r0) * L + l0 + c4]);
        cpa16(Ad + r1 * SPAD + c4, &xb[(size_t)(kt + r1) * L + l0 + c4]);
        cpa16(Bd + r0 * SPAD + c4, &W [(size_t)(kt + r0) * D + j0 + c4]);
        cpa16(Bd + r1 * SPAD + c4, &W [(size_t)(kt + r1) * D + j0 + c4]);
        CPA_COMMIT();
    }

    for (int i = 0; i < 32; i++) {
        int st = i & 3;
        CPA_WAIT2();
        __syncthreads();

        const float* Ast = As + st * STG_F;
        const float* Bst = Bs + st * STG_F;
        #pragma unroll
        for (int ks = 0; ks < 2; ks++) {
            int k0 = ks * 8;
            unsigned afr[4][4], bfr[4][2];
            #pragma unroll
            for (int mt = 0; mt < 4; mt++) {
                int m = wm * 64 + mt * 16 + g;
                afr[mt][0] = f2t(Ast[(k0 + tg    ) * SPAD + m]);
                afr[mt][1] = f2t(Ast[(k0 + tg    ) * SPAD + m + 8]);
                afr[mt][2] = f2t(Ast[(k0 + tg + 4) * SPAD + m]);
                afr[mt][3] = f2t(Ast[(k0 + tg + 4) * SPAD + m + 8]);
            }
            #pragma unroll
            for (int nt = 0; nt < 4; nt++) {
                int n = wn * 32 + nt * 8 + g;
                bfr[nt][0] = f2t(Bst[(k0 + tg    ) * SPAD + n]);
                bfr[nt][1] = f2t(Bst[(k0 + tg + 4) * SPAD + n]);
            }
            #pragma unroll
            for (int mt = 0; mt < 4; mt++)
                #pragma unroll
                for (int nt = 0; nt < 4; nt++)
                    mma_tf32(acc[mt][nt], afr[mt], bfr[nt]);
        }

        if (i + 3 < 32) {
            int kt = (i + 3) * 16;
            int ns = (i + 3) & 3;
            float* Ad = As + ns * STG_F;
            float* Bd = Bs + ns * STG_F;
            cpa16(Ad + r0 * SPAD + c4, &xb[(size_t)(kt + r0) * L + l0 + c4]);
            cpa16(Ad + r1 * SPAD + c4, &xb[(size_t)(kt + r1) * L + l0 + c4]);
            cpa16(Bd + r0 * SPAD + c4, &W [(size_t)(kt + r0) * D + j0 + c4]);
            cpa16(Bd + r1 * SPAD + c4, &W [(size_t)(kt + r1) * D + j0 + c4]);
        }
        CPA_COMMIT();
    }

    float* ob = out + (size_t)b * LP1 * D;
    #pragma unroll
    for (int mt = 0; mt < 4; mt++) {
        int row0 = l0 + wm * 64 + mt * 16 + g;
        #pragma unroll
        for (int nt = 0; nt < 4; nt++) {
            int col = j0 + wn * 32 + nt * 8 + tg * 2;
            *(float2*)&ob[(size_t)row0 * D + col] =
                make_float2(acc[mt][nt][0], acc[mt][nt][1]);
            *(float2*)&ob[(size_t)(row0 + 8) * D + col] =
                make_float2(acc[mt][nt][2], acc[mt][nt][3]);
        }
    }
}

// ---------------------------------------------------------------------------
// Ring output projection (TF32 + cp.async). Both operands row-copied:
//   A = WO rows [d][e-contiguous], B = att_t rows [d][l-contiguous].
// out[b][e][l] = sum_d WO[d][e] * att_t[b][d][l] + bO[e]
// grid: (L/128, D/128, B), 256 threads.
// ---------------------------------------------------------------------------
__global__ void __launch_bounds__(256, 2)
ring_gemm(const float* __restrict__ WO,
          const float* __restrict__ bO,
          float* __restrict__ out) {
    extern __shared__ float sm[];
    float* As = sm;                 // [4][16][SPAD]  (k=d x m=e)
    float* Bs = sm + 4 * STG_F;     // [4][16][SPAD]  (k=d x n=l)

    int b  = blockIdx.z;
    int l0 = blockIdx.x * 128;
    int e0 = blockIdx.y * 128;
    const float* ab = g_att + (size_t)b * D * L;

    int tid  = threadIdx.x;
    int lane = tid & 31, wid = tid >> 5;
    int g    = lane >> 2, tg = lane & 3;
    int wm   = wid & 1,  wn = wid >> 1;
    int r0 = wid, r1 = wid + 8, c4 = lane * 4;

    float acc[4][4][4] = {};

    #pragma unroll
    for (int p = 0; p < 3; p++) {
        int kt = p * 16;
        float* Ad = As + p * STG_F;
        float* Bd = Bs + p * STG_F;
        cpa16(Ad + r0 * SPAD + c4, &WO[(size_t)(kt + r0) * D + e0 + c4]);
        cpa16(Ad + r1 * SPAD + c4, &WO[(size_t)(kt + r1) * D + e0 + c4]);
        cpa16(Bd + r0 * SPAD + c4, &ab[(size_t)(kt + r0) * L + l0 + c4]);
        cpa16(Bd + r1 * SPAD + c4, &ab[(size_t)(kt + r1) * L + l0 + c4]);
        CPA_COMMIT();
    }

    for (int i = 0; i < 32; i++) {
        int st = i & 3;
        CPA_WAIT2();
        __syncthreads();

        const float* Ast = As + st * STG_F;
        const float* Bst = Bs + st * STG_F;
        #pragma unroll
        for (int ks = 0; ks < 2; ks++) {
            int k0 = ks * 8;
            unsigned afr[4][4], bfr[4][2];
            #pragma unroll
            for (int mt = 0; mt < 4; mt++) {
                int m = wm * 64 + mt * 16 + g;
                afr[mt][0] = f2t(Ast[(k0 + tg    ) * SPAD + m]);
                afr[mt][1] = f2t(Ast[(k0 + tg    ) * SPAD + m + 8]);
                afr[mt][2] = f2t(Ast[(k0 + tg + 4) * SPAD + m]);
                afr[mt][3] = f2t(Ast[(k0 + tg + 4) * SPAD + m + 8]);
            }
            #pragma unroll
            for (int nt = 0; nt < 4; nt++) {
                int n = wn * 32 + nt * 8 + g;
                bfr[nt][0] = f2t(Bst[(k0 + tg    ) * SPAD + n]);
                bfr[nt][1] = f2t(Bst[(k0 + tg + 4) * SPAD + n]);
            }
            #pragma unroll
            for (int mt = 0; mt < 4; mt++)
                #pragma unroll
                for (int nt = 0; nt < 4; nt++)
                    mma_tf32(acc[mt][nt], afr[mt], bfr[nt]);
        }

        if (i + 3 < 32) {
            int kt = (i + 3) * 16;
            int ns = (i + 3) & 3;
            float* Ad = As + ns * STG_F;
            float* Bd = Bs + ns * STG_F;
            cpa16(Ad + r0 * SPAD + c4, &WO[(size_t)(kt + r0) * D + e0 + c4]);
            cpa16(Ad + r1 * SPAD + c4, &WO[(size_t)(kt + r1) * D + e0 + c4]);
            cpa16(Bd + r0 * SPAD + c4, &ab[(size_t)(kt + r0) * L + l0 + c4]);
            cpa16(Bd + r1 * SPAD + c4, &ab[(size_t)(kt + r1) * L + l0 + c4]);
        }
        CPA_COMMIT();
    }

    float* outb = out + (size_t)b * D * L;
    #pragma unroll
    for (int mt = 0; mt < 4; mt++) {
        int e = e0 + wm * 64 + mt * 16 + g;
        float bias0 = bO[e];
        float bias1 = bO[e + 8];
        #pragma unroll
        for (int nt = 0; nt < 4; nt++) {
            int col = l0 + wn * 32 + nt * 8 + tg * 2;
            *(float2*)&outb[(size_t)e * L + col] =
                make_float2(acc[mt][nt][0] + bias0, acc[mt][nt][1] + bias0);
            *(float2*)&outb[(size_t)(e + 8) * L + col] =
                make_float2(acc[mt][nt][2] + bias1, acc[mt][nt][3] + bias1);
        }
    }
}

// ---------------------------------------------------------------------------
// QKV relay token. grid: (3, B), block: 512
// ---------------------------------------------------------------------------
__global__ void qkv_relay(const float* __restrict__ y,
                          const float* __restrict__ Wq,
                          const float* __restrict__ Wk,
                          const float* __restrict__ Wv) {
    int z = blockIdx.x, b = blockIdx.y;
    const float* W = (z == 0) ? Wq : (z == 1) ? Wk : Wv;
    float* out = (z == 0) ? g_q : (z == 1) ? g_k : g_v;

    __shared__ float sy[D];
    int t = threadIdx.x;
    sy[t] = y[b * D + t];
    __syncthreads();

    float s = 0.f;
    for (int d = 0; d < D; d++) s += sy[d] * W[(size_t)d * D + t];
    out[(size_t)b * LP1 * D + (size_t)L * D + t] = s;
}

// ---------------------------------------------------------------------------
// Local windowed attention, smem-tiled; output written TRANSPOSED via an
// smem staging buffer (reuses sk after a barrier).
// grid: (L/64, NH, B), 256 threads.
// ---------------------------------------------------------------------------
__global__ void __launch_bounds__(256, 4)
local_attn() {
    __shared__ float2 sk[67][32];
    __shared__ float2 sv[67][32];

    int l0   = blockIdx.x * 64;
    int head = blockIdx.y;
    int b    = blockIdx.z;
    int hoff = head * HD;
    int tid  = threadIdx.x;

    const float* kb = g_k + (size_t)b * LP1 * D + hoff;
    const float* vb = g_v + (size_t)b * LP1 * D + hoff;

    for (int idx = tid; idx < 67 * 16; idx += 256) {
        int r = idx >> 4, c = idx & 15;
        float4 kv = make_float4(0.f, 0.f, 0.f, 0.f), vv = kv;
        int tok = (r == 66) ? L : (l0 - 1 + r);
        if (r == 66 || (unsigned)(l0 - 1 + r) < (unsigned)L) {
            kv = *(const float4*)&kb[(size_t)tok * D + c * 4];
            vv = *(const float4*)&vb[(size_t)tok * D + c * 4];
        }
        ((float4*)sk[r])[c] = kv;
        ((float4*)sv[r])[c] = vv;
    }
    __syncthreads();

    int w = tid >> 5, lane = tid & 31;
    const float* qb = g_q + (size_t)b * LP1 * D + hoff;

    float2 acc2[8];
    #pragma unroll
    for (int t = 0; t < 8; t++) {
        int j = w * 8 + t;
        int l = l0 + j;
        float2 qv = *(const float2*)&qb[(size_t)l * D + lane * 2];

        float s[4];
        #pragma unroll
        for (int w4 = 0; w4 < 4; w4++) {
            int row = (w4 < 3) ? (j + w4) : 66;
            float2 kv = sk[row][lane];
            float sv_ = qv.x * kv.x + qv.y * kv.y;
            #pragma unroll
            for (int o = 16; o > 0; o >>= 1)
                sv_ += __shfl_xor_sync(0xffffffffu, sv_, o);
            s[w4] = sv_ * ATT_SCALE;
        }

        float mx = fmaxf(fmaxf(s[0], s[1]), fmaxf(s[2], s[3]));
        float e[4], denom = 0.f;
        #pragma unroll
        for (int w4 = 0; w4 < 4; w4++) { e[w4] = expf(s[w4] - mx); denom += e[w4]; }
        float inv = 1.f / denom;

        float2 acc = make_float2(0.f, 0.f);
        #pragma unroll
        for (int w4 = 0; w4 < 4; w4++) {
            int row = (w4 < 3) ? (j + w4) : 66;
            float2 vv = sv[row][lane];
            float a = e[w4] * inv;
            acc.x += a * vv.x;
            acc.y += a * vv.y;
        }
        acc2[t] = acc;
    }
    __syncthreads();   // all reads of sk done; safe to alias

    float* sout = (float*)sk;   // [64 tokens][66] (16.9KB within sk's 17.2KB)
    #pragma unroll
    for (int t = 0; t < 8; t++) {
        int j = w * 8 + t;
        sout[j * 66 + lane * 2]     = acc2[t].x;
        sout[j * 66 + lane * 2 + 1] = acc2[t].y;
    }
    __syncthreads();

    // Write transposed: g_att[b][hoff+d][l0+c]
    float* ab = g_att + (size_t)b * D * L;
    int r = tid >> 6, c = tid & 63;
    #pragma unroll
    for (int rr = r; rr < 64; rr += 4)
        ab[(size_t)(hoff + rr) * L + l0 + c] = sout[c * 66 + rr];
}

// ---------------------------------------------------------------------------
// Relay attention split-K partials; phase-1 warp-per-token (coalesced).
// grid: (NH, B, RSPLIT), 256 threads.
// ---------------------------------------------------------------------------
__global__ void relay_partial() {
    int n = blockIdx.x, b = blockIdx.y, z = blockIdx.z;
    int start = z * RCHUNK;
    int end   = min(start + RCHUNK, LP1);

    __shared__ float sq[HD];
    __shared__ float sc[RCHUNK];
    __shared__ float red[256];
    __shared__ float pacc[4][64];

    int tid = threadIdx.x;
    int w = tid >> 5, lane = tid & 31;
    const float* qb = g_q + (size_t)b * LP1 * D;
    const float* kb = g_k + (size_t)b * LP1 * D;
    const float* vb = g_v + (size_t)b * LP1 * D;
    int hoff = n * HD;

    if (tid < HD) sq[tid] = qb[(size_t)L * D + hoff + tid];
    __syncthreads();

    float qx = sq[lane * 2], qy = sq[lane * 2 + 1];
    float lmax = -1e30f;
    for (int l = start + w; l < end; l += 8) {
        float2 kv = *(const float2*)&kb[(size_t)l * D + hoff + lane * 2];
        float dot = qx * kv.x + qy * kv.y;
        #pragma unroll
        for (int o = 16; o > 0; o >>= 1)
            dot += __shfl_xor_sync(0xffffffffu, dot, o);
        dot *= ATT_SCALE;
        if (lane == 0) sc[l - start] = dot;
        lmax = fmaxf(lmax, dot);
    }
    red[tid] = lmax; __syncthreads();
    for (int s = 128; s > 0; s >>= 1) {
        if (tid < s) red[tid] = fmaxf(red[tid], red[tid + s]);
        __syncthreads();
    }
    float mx = red[0];
    __syncthreads();

    float lsum = 0.f;
    for (int l = start + tid; l < end; l += 256) {
        float e = expf(sc[l - start] - mx);
        sc[l - start] = e;
        lsum += e;
    }
    red[tid] = lsum; __syncthreads();
    for (int s = 128; s > 0; s >>= 1) {
        if (tid < s) red[tid] += red[tid + s];
        __syncthreads();
    }
    float sum = red[0];
    __syncthreads();

    int d = tid & 63, g = tid >> 6;
    float part = 0.f;
    for (int l = start + g; l < end; l += 4)
        part += sc[l - start] * vb[(size_t)l * D + hoff + d];
    pacc[g][d] = part;
    __syncthreads();

    int idx = (b * NH + n) * RSPLIT + z;
    if (tid < 64)
        g_ro[(size_t)idx * HD + tid] =
            pacc[0][tid] + pacc[1][tid] + pacc[2][tid] + pacc[3][tid];
    if (tid == 0) { g_rm[idx] = mx; g_rs[idx] = sum; }
}

// ---------------------------------------------------------------------------
// Relay combine (exact merge). grid: B, 512 threads.
// ---------------------------------------------------------------------------
__global__ void relay_combine() {
    int b = blockIdx.x;
    int t = threadIdx.x;
    int n = t >> 6, d = t & 63;
    int base = (b * NH + n) * RSPLIT;

    float M = -1e30f;
    #pragma unroll
    for (int i = 0; i < RSPLIT; i++) M = fmaxf(M, g_rm[base + i]);
    float S = 0.f, O = 0.f;
    #pragma unroll
    for (int i = 0; i < RSPLIT; i++) {
        float w = expf(g_rm[base + i] - M);
        S += g_rs[base + i] * w;
        O += g_ro[(size_t)(base + i) * HD + d] * w;
    }
    g_attr[b * D + n * HD + d] = O / S;
}

// ---------------------------------------------------------------------------
// Relay output projection. grid: B, block: 512.
// ---------------------------------------------------------------------------
__global__ void relay_out(const float* __restrict__ WOs,
                          const float* __restrict__ bOs,
                          float* __restrict__ out) {
    int b = blockIdx.x;
    __shared__ float sa[D];
    int t = threadIdx.x;
    sa[t] = g_attr[b * D + t];
    __syncthreads();
    float s = bOs[t];
    for (int d = 0; d < D; d++) s += sa[d] * WOs[(size_t)d * D + t];
    out[(size_t)B * D * L + b * D + t] = s;
}

// ---------------------------------------------------------------------------
extern "C" void kernel_launch(void* const* d_in, const int* in_sizes, int n_in,
                              void* d_out, int out_size) {
    const float* x       = (const float*)d_in[0];
    const float* y       = (const float*)d_in[1];
    const float* Wq      = (const float*)d_in[2];
    const float* Wk      = (const float*)d_in[3];
    const float* Wv      = (const float*)d_in[4];
    const float* WO_ring = (const float*)d_in[5];
    const float* bO_ring = (const float*)d_in[6];
    const float* WO_star = (const float*)d_in[7];
    const float* bO_star = (const float*)d_in[8];
    float* out = (float*)d_out;

    cudaFuncSetAttribute(qkv_gemm, cudaFuncAttributeMaxDynamicSharedMemorySize, GEMM_SHM);
    cudaFuncSetAttribute(ring_gemm, cudaFuncAttributeMaxDynamicSharedMemorySize, GEMM_SHM);

    qkv_gemm <<<dim3(B * L / 128, D / 128, 3), 256, GEMM_SHM>>>(x, Wq, Wk, Wv);
    qkv_relay<<<dim3(3, B), D>>>(y, Wq, Wk, Wv);
    local_attn<<<dim3(L / 64, NH, B), 256>>>();
    relay_partial<<<dim3(NH, B, RSPLIT), 256>>>();
    ring_gemm<<<dim3(L / 128, D / 128, B), 256, GEMM_SHM>>>(WO_ring, bO_ring, out);
    relay_combine<<<B, 512>>>();
    relay_out<<<B, D>>>(WO_star, bO_star, out);
}

// round 17
// speedup vs baseline: 1.6539x; 1.0327x over previous
#include <cuda_runtime.h>
#include <cstdint>

#define B   8
#define D   512
#define L   4096
#define NH  8
#define HD  64
#define LP1 4097
#define RSPLIT 16
#define RCHUNK 257
#define ATT_SCALE 0.125f

// Scratch (device globals: no runtime allocation allowed)
__device__ float g_q[B * LP1 * D];
__device__ float g_k[B * LP1 * D];
__device__ float g_v[B * LP1 * D];
__device__ float g_att[B * D * L];    // TRANSPOSED (b, d, l), tf32-rounded
__device__ float g_xr[B * D * L];     // tf32-rounded x
__device__ float g_wr[4 * D * D];     // tf32-rounded Wq,Wk,Wv,WO_ring
__device__ float g_attr[B * D];
__device__ float g_rm[B * NH * RSPLIT];
__device__ float g_rs[B * NH * RSPLIT];
__device__ float g_ro[B * NH * RSPLIT * HD];

// ---------------------------------------------------------------------------
// TF32 + cp.async helpers
// ---------------------------------------------------------------------------
__device__ __forceinline__ unsigned f2t(float f) {
    unsigned r;
    asm("cvt.rna.tf32.f32 %0, %1;" : "=r"(r) : "f"(f));
    return r;
}
__device__ __forceinline__ void mma_tf32(float c[4], const unsigned a[4],
                                         const unsigned b[2]) {
    asm volatile(
        "mma.sync.aligned.m16n8k8.row.col.f32.tf32.tf32.f32 "
        "{%0,%1,%2,%3}, {%4,%5,%6,%7}, {%8,%9}, {%0,%1,%2,%3};"
        : "+f"(c[0]), "+f"(c[1]), "+f"(c[2]), "+f"(c[3])
        : "r"(a[0]), "r"(a[1]), "r"(a[2]), "r"(a[3]), "r"(b[0]), "r"(b[1]));
}
__device__ __forceinline__ uint32_t smem_u32(const void* p) {
    uint32_t a;
    asm("{ .reg .u64 t; cvta.to.shared.u64 t, %1; cvt.u32.u64 %0, t; }"
        : "=r"(a) : "l"(p));
    return a;
}
__device__ __forceinline__ void cpa16(float* dst, const float* src) {
    asm volatile("cp.async.cg.shared.global [%0], [%1], 16;"
                 :: "r"(smem_u32(dst)), "l"(src) : "memory");
}
#define CPA_COMMIT() asm volatile("cp.async.commit_group;" ::: "memory")
#define CPA_WAIT2()  asm volatile("cp.async.wait_group 2;"  ::: "memory")

#define SPAD 136                 // smem row pad (floats)
#define STG_F (16 * SPAD)        // floats per stage per matrix
#define GEMM_SHM (4 * STG_F * 2 * 4)   // 4 stages x 2 matrices, bytes = 69632

// ---------------------------------------------------------------------------
// Prep: round x and the 4 GEMM weight matrices to tf32 once.
// All GEMM inputs are then raw-bit loadable (no per-fragment cvt).
// ---------------------------------------------------------------------------
__global__ void prep_x(const float* __restrict__ x) {
    int i = blockIdx.x * 256 + threadIdx.x;          // float4 index
    const float4* src = (const float4*)x;
    float4 v = src[i];
    float4 r = make_float4(__uint_as_float(f2t(v.x)), __uint_as_float(f2t(v.y)),
                           __uint_as_float(f2t(v.z)), __uint_as_float(f2t(v.w)));
    ((float4*)g_xr)[i] = r;
}
__global__ void prep_w(const float* __restrict__ Wq,
                       const float* __restrict__ Wk,
                       const float* __restrict__ Wv,
                       const float* __restrict__ WO) {
    int i = blockIdx.x * 256 + threadIdx.x;          // float4 index over 4*D*D
    int mat = i / (D * D / 4);
    int off = i % (D * D / 4);
    const float4* src = (const float4*)((mat == 0) ? Wq : (mat == 1) ? Wk
                                        : (mat == 2) ? Wv : WO);
    float4 v = src[off];
    float4 r = make_float4(__uint_as_float(f2t(v.x)), __uint_as_float(f2t(v.y)),
                           __uint_as_float(f2t(v.z)), __uint_as_float(f2t(v.w)));
    ((float4*)g_wr)[i] = r;
}

// ---------------------------------------------------------------------------
// QKV projection (TF32 mma.sync + 4-stage cp.async, raw-bit fragments).
//   out[b][l][j] = sum_d xr[b][d][l] * Wr[d][j]
// grid: (B*L/128, D/128, 3), 256 threads (8 warps 2m x 4n, 64x32/warp).
// ---------------------------------------------------------------------------
__global__ void __launch_bounds__(256, 2)
qkv_gemm() {
    extern __shared__ float sm[];
    float* As = sm;                 // [4][16][SPAD]  (k x m=l)
    float* Bs = sm + 4 * STG_F;     // [4][16][SPAD]  (k x n=j)

    int z = blockIdx.z;
    const float* W = g_wr + (size_t)z * D * D;
    float* out = (z == 0) ? g_q : (z == 1) ? g_k : g_v;

    int m0 = blockIdx.x * 128;
    int b  = m0 >> 12;
    int l0 = m0 & (L - 1);
    int j0 = blockIdx.y * 128;
    const float* xb = g_xr + (size_t)b * D * L;

    int tid  = threadIdx.x;
    int lane = tid & 31, wid = tid >> 5;
    int g    = lane >> 2, tg = lane & 3;
    int wm   = wid & 1,  wn = wid >> 1;
    int r0 = wid, r1 = wid + 8, c4 = lane * 4;

    float acc[4][4][4] = {};

    #pragma unroll
    for (int p = 0; p < 3; p++) {
        int kt = p * 16;
        float* Ad = As + p * STG_F;
        float* Bd = Bs + p * STG_F;
        cpa16(Ad + r0 * SPAD + c4, &xb[(size_t)(kt + r0) * L + l0 + c4]);
        cpa16(Ad + r1 * SPAD + c4, &xb[(size_t)(kt + r1) * L + l0 + c4]);
        cpa16(Bd + r0 * SPAD + c4, &W [(size_t)(kt + r0) * D + j0 + c4]);
        cpa16(Bd + r1 * SPAD + c4, &W [(size_t)(kt + r1) * D + j0 + c4]);
        CPA_COMMIT();
    }

    for (int i = 0; i < 32; i++) {
        int st = i & 3;
        CPA_WAIT2();
        __syncthreads();

        const unsigned* Ast = (const unsigned*)(As + st * STG_F);
        const unsigned* Bst = (const unsigned*)(Bs + st * STG_F);
        #pragma unroll
        for (int ks = 0; ks < 2; ks++) {
            int k0 = ks * 8;
            unsigned afr[4][4], bfr[4][2];
            #pragma unroll
            for (int mt = 0; mt < 4; mt++) {
                int m = wm * 64 + mt * 16 + g;
                afr[mt][0] = Ast[(k0 + tg    ) * SPAD + m];
                afr[mt][1] = Ast[(k0 + tg    ) * SPAD + m + 8];
                afr[mt][2] = Ast[(k0 + tg + 4) * SPAD + m];
                afr[mt][3] = Ast[(k0 + tg + 4) * SPAD + m + 8];
            }
            #pragma unroll
            for (int nt = 0; nt < 4; nt++) {
                int n = wn * 32 + nt * 8 + g;
                bfr[nt][0] = Bst[(k0 + tg    ) * SPAD + n];
                bfr[nt][1] = Bst[(k0 + tg + 4) * SPAD + n];
            }
            #pragma unroll
            for (int mt = 0; mt < 4; mt++)
                #pragma unroll
                for (int nt = 0; nt < 4; nt++)
                    mma_tf32(acc[mt][nt], afr[mt], bfr[nt]);
        }

        if (i + 3 < 32) {
            int kt = (i + 3) * 16;
            int ns = (i + 3) & 3;
            float* Ad = As + ns * STG_F;
            float* Bd = Bs + ns * STG_F;
            cpa16(Ad + r0 * SPAD + c4, &xb[(size_t)(kt + r0) * L + l0 + c4]);
            cpa16(Ad + r1 * SPAD + c4, &xb[(size_t)(kt + r1) * L + l0 + c4]);
            cpa16(Bd + r0 * SPAD + c4, &W [(size_t)(kt + r0) * D + j0 + c4]);
            cpa16(Bd + r1 * SPAD + c4, &W [(size_t)(kt + r1) * D + j0 + c4]);
        }
        CPA_COMMIT();
    }

    float* ob = out + (size_t)b * LP1 * D;
    #pragma unroll
    for (int mt = 0; mt < 4; mt++) {
        int row0 = l0 + wm * 64 + mt * 16 + g;
        #pragma unroll
        for (int nt = 0; nt < 4; nt++) {
            int col = j0 + wn * 32 + nt * 8 + tg * 2;
            *(float2*)&ob[(size_t)row0 * D + col] =
                make_float2(acc[mt][nt][0], acc[mt][nt][1]);
            *(float2*)&ob[(size_t)(row0 + 8) * D + col] =
                make_float2(acc[mt][nt][2], acc[mt][nt][3]);
        }
    }
}

// ---------------------------------------------------------------------------
// Ring output projection (TF32 + cp.async, raw-bit fragments).
// out[b][e][l] = sum_d WOr[d][e] * att_t[b][d][l] + bO[e]
// grid: (L/128, D/128, B), 256 threads.
// ---------------------------------------------------------------------------
__global__ void __launch_bounds__(256, 2)
ring_gemm(const float* __restrict__ bO, float* __restrict__ out) {
    extern __shared__ float sm[];
    float* As = sm;                 // [4][16][SPAD]  (k=d x m=e)
    float* Bs = sm + 4 * STG_F;     // [4][16][SPAD]  (k=d x n=l)

    int b  = blockIdx.z;
    int l0 = blockIdx.x * 128;
    int e0 = blockIdx.y * 128;
    const float* ab = g_att + (size_t)b * D * L;
    const float* WO = g_wr + (size_t)3 * D * D;

    int tid  = threadIdx.x;
    int lane = tid & 31, wid = tid >> 5;
    int g    = lane >> 2, tg = lane & 3;
    int wm   = wid & 1,  wn = wid >> 1;
    int r0 = wid, r1 = wid + 8, c4 = lane * 4;

    float acc[4][4][4] = {};

    #pragma unroll
    for (int p = 0; p < 3; p++) {
        int kt = p * 16;
        float* Ad = As + p * STG_F;
        float* Bd = Bs + p * STG_F;
        cpa16(Ad + r0 * SPAD + c4, &WO[(size_t)(kt + r0) * D + e0 + c4]);
        cpa16(Ad + r1 * SPAD + c4, &WO[(size_t)(kt + r1) * D + e0 + c4]);
        cpa16(Bd + r0 * SPAD + c4, &ab[(size_t)(kt + r0) * L + l0 + c4]);
        cpa16(Bd + r1 * SPAD + c4, &ab[(size_t)(kt + r1) * L + l0 + c4]);
        CPA_COMMIT();
    }

    for (int i = 0; i < 32; i++) {
        int st = i & 3;
        CPA_WAIT2();
        __syncthreads();

        const unsigned* Ast = (const unsigned*)(As + st * STG_F);
        const unsigned* Bst = (const unsigned*)(Bs + st * STG_F);
        #pragma unroll
        for (int ks = 0; ks < 2; ks++) {
            int k0 = ks * 8;
            unsigned afr[4][4], bfr[4][2];
            #pragma unroll
            for (int mt = 0; mt < 4; mt++) {
                int m = wm * 64 + mt * 16 + g;
                afr[mt][0] = Ast[(k0 + tg    ) * SPAD + m];
                afr[mt][1] = Ast[(k0 + tg    ) * SPAD + m + 8];
                afr[mt][2] = Ast[(k0 + tg + 4) * SPAD + m];
                afr[mt][3] = Ast[(k0 + tg + 4) * SPAD + m + 8];
            }
            #pragma unroll
            for (int nt = 0; nt < 4; nt++) {
                int n = wn * 32 + nt * 8 + g;
                bfr[nt][0] = Bst[(k0 + tg    ) * SPAD + n];
                bfr[nt][1] = Bst[(k0 + tg + 4) * SPAD + n];
            }
            #pragma unroll
            for (int mt = 0; mt < 4; mt++)
                #pragma unroll
                for (int nt = 0; nt < 4; nt++)
                    mma_tf32(acc[mt][nt], afr[mt], bfr[nt]);
        }

        if (i + 3 < 32) {
            int kt = (i + 3) * 16;
            int ns = (i + 3) & 3;
            float* Ad = As + ns * STG_F;
            float* Bd = Bs + ns * STG_F;
            cpa16(Ad + r0 * SPAD + c4, &WO[(size_t)(kt + r0) * D + e0 + c4]);
            cpa16(Ad + r1 * SPAD + c4, &WO[(size_t)(kt + r1) * D + e0 + c4]);
            cpa16(Bd + r0 * SPAD + c4, &ab[(size_t)(kt + r0) * L + l0 + c4]);
            cpa16(Bd + r1 * SPAD + c4, &ab[(size_t)(kt + r1) * L + l0 + c4]);
        }
        CPA_COMMIT();
    }

    float* outb = out + (size_t)b * D * L;
    #pragma unroll
    for (int mt = 0; mt < 4; mt++) {
        int e = e0 + wm * 64 + mt * 16 + g;
        float bias0 = bO[e];
        float bias1 = bO[e + 8];
        #pragma unroll
        for (int nt = 0; nt < 4; nt++) {
            int col = l0 + wn * 32 + nt * 8 + tg * 2;
            *(float2*)&outb[(size_t)e * L + col] =
                make_float2(acc[mt][nt][0] + bias0, acc[mt][nt][1] + bias0);
            *(float2*)&outb[(size_t)(e + 8) * L + col] =
                make_float2(acc[mt][nt][2] + bias1, acc[mt][nt][3] + bias1);
        }
    }
}

// ---------------------------------------------------------------------------
// QKV relay token. grid: (3, B), block: 512
// ---------------------------------------------------------------------------
__global__ void qkv_relay(const float* __restrict__ y,
                          const float* __restrict__ Wq,
                          const float* __restrict__ Wk,
                          const float* __restrict__ Wv) {
    int z = blockIdx.x, b = blockIdx.y;
    const float* W = (z == 0) ? Wq : (z == 1) ? Wk : Wv;
    float* out = (z == 0) ? g_q : (z == 1) ? g_k : g_v;

    __shared__ float sy[D];
    int t = threadIdx.x;
    sy[t] = y[b * D + t];
    __syncthreads();

    float s = 0.f;
    for (int d = 0; d < D; d++) s += sy[d] * W[(size_t)d * D + t];
    out[(size_t)b * LP1 * D + (size_t)L * D + t] = s;
}

// ---------------------------------------------------------------------------
// Local windowed attention; output transposed AND tf32-rounded (ring input).
// grid: (L/64, NH, B), 256 threads.
// ---------------------------------------------------------------------------
__global__ void __launch_bounds__(256, 4)
local_attn() {
    __shared__ float2 sk[67][32];
    __shared__ float2 sv[67][32];

    int l0   = blockIdx.x * 64;
    int head = blockIdx.y;
    int b    = blockIdx.z;
    int hoff = head * HD;
    int tid  = threadIdx.x;

    const float* kb = g_k + (size_t)b * LP1 * D + hoff;
    const float* vb = g_v + (size_t)b * LP1 * D + hoff;

    for (int idx = tid; idx < 67 * 16; idx += 256) {
        int r = idx >> 4, c = idx & 15;
        float4 kv = make_float4(0.f, 0.f, 0.f, 0.f), vv = kv;
        int tok = (r == 66) ? L : (l0 - 1 + r);
        if (r == 66 || (unsigned)(l0 - 1 + r) < (unsigned)L) {
            kv = *(const float4*)&kb[(size_t)tok * D + c * 4];
            vv = *(const float4*)&vb[(size_t)tok * D + c * 4];
        }
        ((float4*)sk[r])[c] = kv;
        ((float4*)sv[r])[c] = vv;
    }
    __syncthreads();

    int w = tid >> 5, lane = tid & 31;
    const float* qb = g_q + (size_t)b * LP1 * D + hoff;

    float2 acc2[8];
    #pragma unroll
    for (int t = 0; t < 8; t++) {
        int j = w * 8 + t;
        int l = l0 + j;
        float2 qv = *(const float2*)&qb[(size_t)l * D + lane * 2];

        float s[4];
        #pragma unroll
        for (int w4 = 0; w4 < 4; w4++) {
            int row = (w4 < 3) ? (j + w4) : 66;
            float2 kv = sk[row][lane];
            float sv_ = qv.x * kv.x + qv.y * kv.y;
            #pragma unroll
            for (int o = 16; o > 0; o >>= 1)
                sv_ += __shfl_xor_sync(0xffffffffu, sv_, o);
            s[w4] = sv_ * ATT_SCALE;
        }

        float mx = fmaxf(fmaxf(s[0], s[1]), fmaxf(s[2], s[3]));
        float e[4], denom = 0.f;
        #pragma unroll
        for (int w4 = 0; w4 < 4; w4++) { e[w4] = expf(s[w4] - mx); denom += e[w4]; }
        float inv = 1.f / denom;

        float2 acc = make_float2(0.f, 0.f);
        #pragma unroll
        for (int w4 = 0; w4 < 4; w4++) {
            int row = (w4 < 3) ? (j + w4) : 66;
            float2 vv = sv[row][lane];
            float a = e[w4] * inv;
            acc.x += a * vv.x;
            acc.y += a * vv.y;
        }
        acc2[t] = acc;
    }
    __syncthreads();   // all reads of sk done; safe to alias

    float* sout = (float*)sk;   // [64 tokens][66]
    #pragma unroll
    for (int t = 0; t < 8; t++) {
        int j = w * 8 + t;
        sout[j * 66 + lane * 2]     = acc2[t].x;
        sout[j * 66 + lane * 2 + 1] = acc2[t].y;
    }
    __syncthreads();

    // Write transposed + tf32-rounded: g_att[b][hoff+d][l0+c]
    float* ab = g_att + (size_t)b * D * L;
    int r = tid >> 6, c = tid & 63;
    #pragma unroll
    for (int rr = r; rr < 64; rr += 4)
        ab[(size_t)(hoff + rr) * L + l0 + c] = __uint_as_float(f2t(sout[c * 66 + rr]));
}

// ---------------------------------------------------------------------------
// Relay attention split-K partials (warp-per-token phase 1).
// grid: (NH, B, RSPLIT), 256 threads.
// ---------------------------------------------------------------------------
__global__ void relay_partial() {
    int n = blockIdx.x, b = blockIdx.y, z = blockIdx.z;
    int start = z * RCHUNK;
    int end   = min(start + RCHUNK, LP1);

    __shared__ float sq[HD];
    __shared__ float sc[RCHUNK];
    __shared__ float red[256];
    __shared__ float pacc[4][64];

    int tid = threadIdx.x;
    int w = tid >> 5, lane = tid & 31;
    const float* qb = g_q + (size_t)b * LP1 * D;
    const float* kb = g_k + (size_t)b * LP1 * D;
    const float* vb = g_v + (size_t)b * LP1 * D;
    int hoff = n * HD;

    if (tid < HD) sq[tid] = qb[(size_t)L * D + hoff + tid];
    __syncthreads();

    float qx = sq[lane * 2], qy = sq[lane * 2 + 1];
    float lmax = -1e30f;
    for (int l = start + w; l < end; l += 8) {
        float2 kv = *(const float2*)&kb[(size_t)l * D + hoff + lane * 2];
        float dot = qx * kv.x + qy * kv.y;
        #pragma unroll
        for (int o = 16; o > 0; o >>= 1)
            dot += __shfl_xor_sync(0xffffffffu, dot, o);
        dot *= ATT_SCALE;
        if (lane == 0) sc[l - start] = dot;
        lmax = fmaxf(lmax, dot);
    }
    red[tid] = lmax; __syncthreads();
    for (int s = 128; s > 0; s >>= 1) {
        if (tid < s) red[tid] = fmaxf(red[tid], red[tid + s]);
        __syncthreads();
    }
    float mx = red[0];
    __syncthreads();

    float lsum = 0.f;
    for (int l = start + tid; l < end; l += 256) {
        float e = expf(sc[l - start] - mx);
        sc[l - start] = e;
        lsum += e;
    }
    red[tid] = lsum; __syncthreads();
    for (int s = 128; s > 0; s >>= 1) {
        if (tid < s) red[tid] += red[tid + s];
        __syncthreads();
    }
    float sum = red[0];
    __syncthreads();

    int d = tid & 63, g = tid >> 6;
    float part = 0.f;
    for (int l = start + g; l < end; l += 4)
        part += sc[l - start] * vb[(size_t)l * D + hoff + d];
    pacc[g][d] = part;
    __syncthreads();

    int idx = (b * NH + n) * RSPLIT + z;
    if (tid < 64)
        g_ro[(size_t)idx * HD + tid] =
            pacc[0][tid] + pacc[1][tid] + pacc[2][tid] + pacc[3][tid];
    if (tid == 0) { g_rm[idx] = mx; g_rs[idx] = sum; }
}

// ---------------------------------------------------------------------------
// Relay combine (exact merge). grid: B, 512 threads.
// ---------------------------------------------------------------------------
__global__ void relay_combine() {
    int b = blockIdx.x;
    int t = threadIdx.x;
    int n = t >> 6, d = t & 63;
    int base = (b * NH + n) * RSPLIT;

    float M = -1e30f;
    #pragma unroll
    for (int i = 0; i < RSPLIT; i++) M = fmaxf(M, g_rm[base + i]);
    float S = 0.f, O = 0.f;
    #pragma unroll
    for (int i = 0; i < RSPLIT; i++) {
        float w = expf(g_rm[base + i] - M);
        S += g_rs[base + i] * w;
        O += g_ro[(size_t)(base + i) * HD + d] * w;
    }
    g_attr[b * D + n * HD + d] = O / S;
}

// ---------------------------------------------------------------------------
// Relay output projection. grid: B, block: 512.
// ---------------------------------------------------------------------------
__global__ void relay_out(const float* __restrict__ WOs,
                          const float* __restrict__ bOs,
                          float* __restrict__ out) {
    int b = blockIdx.x;
    __shared__ float sa[D];
    int t = threadIdx.x;
    sa[t] = g_attr[b * D + t];
    __syncthreads();
    float s = bOs[t];
    for (int d = 0; d < D; d++) s += sa[d] * WOs[(size_t)d * D + t];
    out[(size_t)B * D * L + b * D + t] = s;
}

// ---------------------------------------------------------------------------
extern "C" void kernel_launch(void* const* d_in, const int* in_sizes, int n_in,
                              void* d_out, int out_size) {
    const float* x       = (const float*)d_in[0];
    const float* y       = (const float*)d_in[1];
    const float* Wq      = (const float*)d_in[2];
    const float* Wk      = (const float*)d_in[3];
    const float* Wv      = (const float*)d_in[4];
    const float* WO_ring = (const float*)d_in[5];
    const float* bO_ring = (const float*)d_in[6];
    const float* WO_star = (const float*)d_in[7];
    const float* bO_star = (const float*)d_in[8];
    float* out = (float*)d_out;

    cudaFuncSetAttribute(qkv_gemm, cudaFuncAttributeMaxDynamicSharedMemorySize, GEMM_SHM);
    cudaFuncSetAttribute(ring_gemm, cudaFuncAttributeMaxDynamicSharedMemorySize, GEMM_SHM);

    prep_x<<<B * D * L / 4 / 256, 256>>>(x);
    prep_w<<<4 * D * D / 4 / 256, 256>>>(Wq, Wk, Wv, WO_ring);
    qkv_gemm <<<dim3(B * L / 128, D / 128, 3), 256, GEMM_SHM>>>();
    qkv_relay<<<dim3(3, B), D>>>(y, Wq, Wk, Wv);
    local_attn<<<dim3(L / 64, NH, B), 256>>>();
    relay_partial<<<dim3(NH, B, RSPLIT), 256>>>();
    ring_gemm<<<dim3(L / 128, D / 128, B), 256, GEMM_SHM>>>(bO_ring, out);
    relay_combine<<<B, 512>>>();
    relay_out<<<B, D>>>(WO_star, bO_star, out);
}